// round 12
// baseline (speedup 1.0000x reference)
#include <cuda_runtime.h>

#define E_TOTAL   20000
#define FDIM      17
#define TILE_E    40
#define CO_TILE   4            // co channels per CTA (grid.y = 8)
#define W3S_ROWS  384          // CO_TILE*32*3
#define W3S_PITCH 33           // padded row (stride 33 -> conflict-free)
#define B_PITCH   36           // [dd][di] triples, each 16B-aligned: dd*12+di*4+q
#define SMEM_FLOATS (W3S_ROWS*W3S_PITCH + TILE_E*32 + TILE_E*B_PITCH)
#define SMEM_BYTES  (SMEM_FLOATS * 4)

// scratch for h2 (radial MLP output), allocation-free per harness rules
__device__ float g_h[E_TOTAL * 32];

// ---------------------------------------------------------------------------
// Kernel 1: radial MLP  f[E,17] -> h2[E,32]. One warp per edge.
// ---------------------------------------------------------------------------
__global__ __launch_bounds__(256) void mlp_kernel(
    const float* __restrict__ f,
    const float* __restrict__ w1, const float* __restrict__ b1,
    const float* __restrict__ g1, const float* __restrict__ be1,
    const float* __restrict__ w2, const float* __restrict__ b2,
    const float* __restrict__ g2, const float* __restrict__ be2)
{
    __shared__ float w1s[32 * FDIM];
    __shared__ float w2s[32 * 33];
    __shared__ float b1s[32], g1s[32], be1s[32];
    __shared__ float b2s[32], g2s[32], be2s[32];

    int tid = threadIdx.x;
    for (int i = tid; i < 32 * FDIM; i += 256) w1s[i] = w1[i];
    for (int i = tid; i < 32 * 32;  i += 256) w2s[(i >> 5) * 33 + (i & 31)] = w2[i];
    if (tid < 32) {
        b1s[tid] = b1[tid]; g1s[tid] = g1[tid]; be1s[tid] = be1[tid];
        b2s[tid] = b2[tid]; g2s[tid] = g2[tid]; be2s[tid] = be2[tid];
    }
    __syncthreads();

    int warp = tid >> 5, lane = tid & 31;
    int e = blockIdx.x * 8 + warp;
    if (e >= E_TOTAL) return;

    float fv = (lane < FDIM) ? f[e * FDIM + lane] : 0.0f;
    float h = b1s[lane];
    #pragma unroll
    for (int k = 0; k < FDIM; k++) {
        float fk = __shfl_sync(0xffffffffu, fv, k);
        h = fmaf(fk, w1s[lane * FDIM + k], h);
    }
    float s = h;
    #pragma unroll
    for (int o = 16; o > 0; o >>= 1) s += __shfl_xor_sync(0xffffffffu, s, o);
    float mu = s * (1.0f / 32.0f);
    float d = h - mu;
    float v = d * d;
    #pragma unroll
    for (int o = 16; o > 0; o >>= 1) v += __shfl_xor_sync(0xffffffffu, v, o);
    float x = d * rsqrtf(v * (1.0f / 32.0f) + 1e-5f) * g1s[lane] + be1s[lane];
    x = fmaxf(x, 0.0f);

    float h2 = b2s[lane];
    #pragma unroll
    for (int k = 0; k < 32; k++) {
        float xk = __shfl_sync(0xffffffffu, x, k);
        h2 = fmaf(xk, w2s[lane * 33 + k], h2);
    }
    s = h2;
    #pragma unroll
    for (int o = 16; o > 0; o >>= 1) s += __shfl_xor_sync(0xffffffffu, s, o);
    mu = s * (1.0f / 32.0f);
    d = h2 - mu;
    v = d * d;
    #pragma unroll
    for (int o = 16; o > 0; o >>= 1) v += __shfl_xor_sync(0xffffffffu, v, o);
    float x2 = d * rsqrtf(v * (1.0f / 32.0f) + 1e-5f) * g2s[lane] + be2s[lane];
    x2 = fmaxf(x2, 0.0f);

    g_h[e * 32 + lane] = x2;
}

// ---------------------------------------------------------------------------
// Kernel 2: k-split conv. grid = (E/TILE_E, 32/CO_TILE), 256 threads.
// warp = (co_r, ci-half); lane = ci_local*2 + kh. Each thread caches 3 w3
// rows x 16 k (48 regs), accumulates partial dots, combines via shfl_xor(1),
// splits the 9-output epilogue 4/5 across the kh pair.
// ---------------------------------------------------------------------------
__global__ __launch_bounds__(256, 3) void conv_kernel(
    const float* __restrict__ basis,
    const float* __restrict__ w3,
    const float* __restrict__ b3,
    float* __restrict__ out)
{
    extern __shared__ float smem[];
    float* w3s = smem;                           // 384 * 33
    float* h_s = smem + W3S_ROWS * W3S_PITCH;    // TILE_E * 32
    float* B_s = h_s + TILE_E * 32;              // TILE_E * 36

    int tid = threadIdx.x;
    int e0  = blockIdx.x * TILE_E;
    int cy  = blockIdx.y;                        // 0..7

    const float* w3g = w3 + (size_t)cy * (W3S_ROWS * 32);
    for (int i = tid; i < W3S_ROWS * 32; i += 256)
        w3s[(i >> 5) * W3S_PITCH + (i & 31)] = w3g[i];
    for (int i = tid; i < TILE_E * 32; i += 256)
        h_s[i] = g_h[(size_t)e0 * 32 + i];
    for (int i = tid; i < TILE_E * 27; i += 256) {
        int el = i / 27, j = i - el * 27;        // j = dd*9 + di*3 + q
        int dd = j / 9,  r = j - dd * 9;
        int di = r / 3,  q = r - di * 3;
        B_s[el * B_PITCH + dd * 12 + di * 4 + q] = basis[(size_t)e0 * 27 + i];
    }
    __syncthreads();

    int warp = tid >> 5, lane = tid & 31;
    int co_r = warp >> 1;                        // 0..3
    int wh   = warp & 1;                         // which ci half
    int cil  = lane >> 1;                        // 0..15
    int kh   = lane & 1;                         // k half
    int ci   = wh * 16 + cil;
    int co   = cy * CO_TILE + co_r;

    // cache 3 w3 rows x 16 k  (conflict-free: bank = 3*cil + 16*kh + c)
    int row0 = (co_r * 32 + ci) * 3;
    float w3r[48];
    #pragma unroll
    for (int ff = 0; ff < 3; ff++) {
        const float* wr = w3s + (row0 + ff) * W3S_PITCH + kh * 16;
        #pragma unroll
        for (int k = 0; k < 16; k++)
            w3r[ff * 16 + k] = wr[k];
    }

    size_t jb = ((size_t)co * 32 + ci) * 3;
    float b30 = b3[jb], b31 = b3[jb + 1], b32 = b3[jb + 2];

    float* outb = out + (size_t)e0 * 9216 + (size_t)(co * 3) * 96 + ci * 3;

    for (int e = 0; e < TILE_E; e++) {
        // ---- partial GEMM over this thread's 16 k's ----
        const float* hp = h_s + e * 32 + kh * 16;
        float P0 = 0.0f, P1 = 0.0f, P2 = 0.0f;
        #pragma unroll
        for (int k4 = 0; k4 < 4; k4++) {
            float4 hv = *reinterpret_cast<const float4*>(hp + k4 * 4);
            P0 = fmaf(hv.x, w3r[ 0 + k4 * 4 + 0], P0);
            P1 = fmaf(hv.x, w3r[16 + k4 * 4 + 0], P1);
            P2 = fmaf(hv.x, w3r[32 + k4 * 4 + 0], P2);
            P0 = fmaf(hv.y, w3r[ 0 + k4 * 4 + 1], P0);
            P1 = fmaf(hv.y, w3r[16 + k4 * 4 + 1], P1);
            P2 = fmaf(hv.y, w3r[32 + k4 * 4 + 1], P2);
            P0 = fmaf(hv.z, w3r[ 0 + k4 * 4 + 2], P0);
            P1 = fmaf(hv.z, w3r[16 + k4 * 4 + 2], P1);
            P2 = fmaf(hv.z, w3r[32 + k4 * 4 + 2], P2);
            P0 = fmaf(hv.w, w3r[ 0 + k4 * 4 + 3], P0);
            P1 = fmaf(hv.w, w3r[16 + k4 * 4 + 3], P1);
            P2 = fmaf(hv.w, w3r[32 + k4 * 4 + 3], P2);
        }
        // ---- combine k-halves (partner = lane^1) and add bias ----
        float R0 = P0 + __shfl_xor_sync(0xffffffffu, P0, 1) + b30;
        float R1 = P1 + __shfl_xor_sync(0xffffffffu, P1, 1) + b31;
        float R2 = P2 + __shfl_xor_sync(0xffffffffu, P2, 1) + b32;

        // ---- epilogue: (dd,di) triples as single LDS.128; 4/5 split ----
        const float4* Bq = reinterpret_cast<const float4*>(B_s + e * B_PITCH);
        float* op = outb + (size_t)e * 9216;
        if (kh == 0) {
            #pragma unroll
            for (int di = 0; di < 3; di++) {
                float4 t = Bq[0 * 3 + di];                       // B[0][di][0..2]
                op[0 * 96 + di] = fmaf(R2, t.z, fmaf(R1, t.y, R0 * t.x));
            }
            float4 t = Bq[2 * 3 + 0];                            // B[2][0]
            op[2 * 96 + 0] = fmaf(R2, t.z, fmaf(R1, t.y, R0 * t.x));
        } else {
            #pragma unroll
            for (int di = 0; di < 3; di++) {
                float4 t = Bq[1 * 3 + di];                       // B[1][di]
                op[1 * 96 + di] = fmaf(R2, t.z, fmaf(R1, t.y, R0 * t.x));
            }
            #pragma unroll
            for (int di = 1; di < 3; di++) {
                float4 t = Bq[2 * 3 + di];                       // B[2][1..2]
                op[2 * 96 + di] = fmaf(R2, t.z, fmaf(R1, t.y, R0 * t.x));
            }
        }
    }
}

// ---------------------------------------------------------------------------
extern "C" void kernel_launch(void* const* d_in, const int* in_sizes, int n_in,
                              void* d_out, int out_size)
{
    const float* f     = (const float*)d_in[0];
    const float* basis = (const float*)d_in[1];
    const float* w1    = (const float*)d_in[2];
    const float* b1    = (const float*)d_in[3];
    const float* g1    = (const float*)d_in[4];
    const float* be1   = (const float*)d_in[5];
    const float* w2    = (const float*)d_in[6];
    const float* b2    = (const float*)d_in[7];
    const float* g2    = (const float*)d_in[8];
    const float* be2   = (const float*)d_in[9];
    const float* w3    = (const float*)d_in[10];
    const float* b3    = (const float*)d_in[11];
    float* out = (float*)d_out;

    mlp_kernel<<<(E_TOTAL + 7) / 8, 256>>>(f, w1, b1, g1, be1, w2, b2, g2, be2);

    cudaFuncSetAttribute(conv_kernel,
                         cudaFuncAttributeMaxDynamicSharedMemorySize, SMEM_BYTES);
    dim3 grid(E_TOTAL / TILE_E, 32 / CO_TILE);
    conv_kernel<<<grid, 256, SMEM_BYTES>>>(basis, w3, b3, out);
}